// round 15
// baseline (speedup 1.0000x reference)
#include <cuda_runtime.h>
#include <cuda_fp16.h>
#include <cstdint>

#define T_ITER 8
#define L_DIM  4096
#define D_DIM  512
#define H_DIM  256
#define M_TOT  (T_ITER * L_DIM)

// ---------------- scratch ----------------
__device__ __half  g_Ah[(size_t)M_TOT * D_DIM];         // emb f16, 32 MB
__device__ __half  g_E[(size_t)M_TOT * H_DIM];          // emb @ Ws, f16, 16 MB
__device__ float   g_dxyz[(size_t)M_TOT * 3];
__device__ float   g_pa[2 * M_TOT];                     // gate logit, 2 col-halves
__device__ __half  g_Bh[H_DIM * D_DIM];                 // Ws^T f16, [n][k]

__device__ __forceinline__ float tanhap(float x) {
    float y; asm("tanh.approx.f32 %0, %1;" : "=f"(y) : "f"(x)); return y;
}

// ---------------- kernel 0: prep (A fp32->f16 + dec dots) UNION Ws transpose --------
__global__ void __launch_bounds__(256) k_prep(const float* __restrict__ A,
                                              const float* __restrict__ Wx,
                                              const float* __restrict__ Wy,
                                              const float* __restrict__ Wz,
                                              const float* __restrict__ Ws) {
    __shared__ float sw[3][D_DIM];
    const int tid = threadIdx.x, lane = tid & 31;
    if (blockIdx.x >= L_DIM) {
        // ---- Ws (512x256 [k][n]) -> g_Bh ([n][k]) f16 ----
        const int cb = blockIdx.x - L_DIM;       // 0..127
        const int bx = cb & 7, by = cb >> 3;
        const int tx = tid & 31, ty = tid >> 5;  // 32 x 8
        float (*tile)[33] = (float(*)[33])sw;
        #pragma unroll
        for (int i = 0; i < 4; i++) {
            int k = by * 32 + ty + i * 8;
            tile[ty + i * 8][tx] = Ws[k * H_DIM + bx * 32 + tx];
        }
        __syncthreads();
        #pragma unroll
        for (int i = 0; i < 4; i++) {
            int n = bx * 32 + ty + i * 8;
            g_Bh[n * D_DIM + by * 32 + tx] = __float2half(tile[tx][ty + i * 8]);
        }
        return;
    }
    const int l = blockIdx.x;
    const int t = tid >> 5;                      // warp = time step
    for (int i = tid; i < D_DIM; i += 256) {
        sw[0][i] = Wx[(size_t)l * D_DIM + i];
        sw[1][i] = Wy[(size_t)l * D_DIM + i];
        sw[2][i] = Wz[(size_t)l * D_DIM + i];
    }
    __syncthreads();

    const size_t row = (size_t)t * L_DIM + l;
    const float* a = A + row * D_DIM;
    __half* ah = g_Ah + row * D_DIM;
    float dx = 0.f, dy = 0.f, dz = 0.f;
    #pragma unroll
    for (int j = 0; j < 4; j++) {
        int off = j * 128 + lane * 4;
        float4 v = *(const float4*)(a + off);
        dx += v.x * sw[0][off] + v.y * sw[0][off+1] + v.z * sw[0][off+2] + v.w * sw[0][off+3];
        dy += v.x * sw[1][off] + v.y * sw[1][off+1] + v.z * sw[1][off+2] + v.w * sw[1][off+3];
        dz += v.x * sw[2][off] + v.y * sw[2][off+1] + v.z * sw[2][off+2] + v.w * sw[2][off+3];
        __half2 h0 = __float22half2_rn(make_float2(v.x, v.y));
        __half2 h1 = __float22half2_rn(make_float2(v.z, v.w));
        *(uint2*)(ah + off) = make_uint2(*(uint32_t*)&h0, *(uint32_t*)&h1);
    }
    #pragma unroll
    for (int o = 16; o > 0; o >>= 1) {
        dx += __shfl_xor_sync(0xffffffffu, dx, o);
        dy += __shfl_xor_sync(0xffffffffu, dy, o);
        dz += __shfl_xor_sync(0xffffffffu, dz, o);
    }
    if (lane == 0) {
        g_dxyz[row * 3 + 0] = dx;
        g_dxyz[row * 3 + 1] = dy;
        g_dxyz[row * 3 + 2] = dz;
    }
}

// ---------------- kernel 1: async f16 GEMM, occ 4, single wave, 2-stage overlap -----
#define BM 128
#define BN 128
#define BK 32
#define SAS 40                                   // row stride in b16 (80 B)
#define SZ_A (BM * SAS * 2)                      // 10240
#define SZ_B (BN * SAS * 2)                      // 10240
#define SZ_STG (SZ_A + SZ_B)                     // 20480
#define NSTAGE 2
#define OFF_SPA (NSTAGE * SZ_STG)
#define SMEM_TOTAL (OFF_SPA + BM * 4 * 4)        // 43008
#define NKT (D_DIM / BK)                         // 16

__device__ __forceinline__ void mma_f16acc(uint32_t c[2],
                                           uint32_t a0, uint32_t a1, uint32_t a2, uint32_t a3,
                                           uint32_t b0, uint32_t b1) {
    asm volatile(
        "mma.sync.aligned.m16n8k16.row.col.f16.f16.f16.f16 "
        "{%0,%1}, {%2,%3,%4,%5}, {%6,%7}, {%0,%1};\n"
        : "+r"(c[0]), "+r"(c[1])
        : "r"(a0), "r"(a1), "r"(a2), "r"(a3), "r"(b0), "r"(b1));
}
__device__ __forceinline__ void ldsm_x4(uint32_t addr, uint32_t& r0, uint32_t& r1,
                                        uint32_t& r2, uint32_t& r3) {
    asm volatile("ldmatrix.sync.aligned.m8n8.x4.shared.b16 {%0,%1,%2,%3}, [%4];"
                 : "=r"(r0), "=r"(r1), "=r"(r2), "=r"(r3) : "r"(addr));
}
__device__ __forceinline__ void cp16(uint32_t dst, const void* src) {
    asm volatile("cp.async.ca.shared.global [%0], [%1], 16;" :: "r"(dst), "l"(src) : "memory");
}

__global__ void __launch_bounds__(256, 4) k_gemm(const float* __restrict__ Wh,
                                                 const float* __restrict__ bs) {
    extern __shared__ __align__(128) char smem[];
    uint32_t sbase;
    asm("{ .reg .u64 t; cvta.to.shared.u64 t, %1; cvt.u32.u64 %0, t; }" : "=r"(sbase) : "l"(smem));

    const int tid  = threadIdx.x;
    const int lane = tid & 31, wid = tid >> 5;
    const int grp  = lane >> 2, tig = lane & 3;
    const int nh    = blockIdx.x;                 // N half (fastest -> L2 shares Ah)
    const int lbase = blockIdx.y * 16;            // 16 l's x 8 t's

    // A staging: thread covers 32 B of local row (tid>>1)
    const int arow = tid >> 1;
    const int ahalf = (tid & 1) * 32;
    const size_t argRow = (size_t)(arow >> 4) * L_DIM + lbase + (arow & 15);
    const __half* Asrc = g_Ah + argRow * D_DIM;
    const uint32_t aDst = (uint32_t)(arow * 80) + ahalf;
    // B staging: thread covers 32 B of local row (tid>>1)
    const __half* Bsrc = g_Bh + (size_t)(nh * BN + arow) * D_DIM;
    const uint32_t bDst = aDst;

    const int aRowL = lane & 15;
    const int aColL = (lane >> 4) << 3;
    const int bRowL = (lane & 7) + ((lane >> 4) << 3);
    const int bColL = ((lane >> 3) & 1) << 3;
    const uint32_t stg0 = sbase, stg1 = sbase + SZ_STG;

    // warp tile 64x32: 2 M-warps x 4 N-warps
    const int wm = (wid & 1) * 64;
    const int wn = (wid >> 1) * 32;

    uint32_t acc[4][4][2];
    #pragma unroll
    for (int i = 0; i < 4; i++)
        #pragma unroll
        for (int j = 0; j < 4; j++) { acc[i][j][0] = 0u; acc[i][j][1] = 0u; }

    // ---- prologue: issue kt=0 into stage 0 ----
    cp16(stg0 + aDst,      (const char*)(Asrc) + ahalf);
    cp16(stg0 + aDst + 16, (const char*)(Asrc) + ahalf + 16);
    cp16(stg0 + SZ_A + bDst,      (const char*)(Bsrc) + ahalf);
    cp16(stg0 + SZ_A + bDst + 16, (const char*)(Bsrc) + ahalf + 16);
    asm volatile("cp.async.commit_group;" ::: "memory");

    for (int kt = 0; kt < NKT; kt++) {
        const uint32_t s  = (kt & 1) ? stg1 : stg0;
        const uint32_t sn = (kt & 1) ? stg0 : stg1;
        // issue kt+1 into sn (trailing barrier of iter kt-1 guarantees all warps
        // finished computing from sn)
        if (kt + 1 < NKT) {
            cp16(sn + aDst,      (const char*)(Asrc + (kt + 1) * BK) + ahalf);
            cp16(sn + aDst + 16, (const char*)(Asrc + (kt + 1) * BK) + ahalf + 16);
            cp16(sn + SZ_A + bDst,      (const char*)(Bsrc + (kt + 1) * BK) + ahalf);
            cp16(sn + SZ_A + bDst + 16, (const char*)(Bsrc + (kt + 1) * BK) + ahalf + 16);
        }
        asm volatile("cp.async.commit_group;" ::: "memory");
        asm volatile("cp.async.wait_group 1;" ::: "memory");   // kt done; kt+1 in flight
        __syncthreads();                                       // all threads' kt copies visible

        #pragma unroll
        for (int ks = 0; ks < 2; ks++) {
            uint32_t bf[4][2];
            #pragma unroll
            for (int p = 0; p < 2; p++) {
                uint32_t addr = s + SZ_A + 2u * ((wn + p * 16 + bRowL) * SAS + ks * 16 + bColL);
                ldsm_x4(addr, bf[2*p][0], bf[2*p][1], bf[2*p+1][0], bf[2*p+1][1]);
            }
            #pragma unroll
            for (int mi = 0; mi < 4; mi++) {
                uint32_t a0, a1, a2, a3;
                uint32_t addr = s + 2u * ((wm + mi * 16 + aRowL) * SAS + ks * 16 + aColL);
                ldsm_x4(addr, a0, a1, a2, a3);
                #pragma unroll
                for (int ni = 0; ni < 4; ni++)
                    mma_f16acc(acc[mi][ni], a0, a1, a2, a3, bf[ni][0], bf[ni][1]);
            }
        }
        __syncthreads();                                       // protect sn before next overwrite
    }

    // ---- epilogue: store E (raw f16 accs) + pa partials ----
    float* spa = (float*)(smem + OFF_SPA);        // [128][4]
    float pap[8];
    #pragma unroll
    for (int j = 0; j < 8; j++) pap[j] = 0.f;
    #pragma unroll
    for (int mi = 0; mi < 4; mi++) {
        const int r0 = wm + mi * 16 + grp;
        const int r1 = r0 + 8;
        const size_t rg0 = (size_t)(r0 >> 4) * L_DIM + lbase + (r0 & 15);
        const size_t rg1 = (size_t)(r1 >> 4) * L_DIM + lbase + (r1 & 15);
        const float* wh0 = Wh + (size_t)(lbase + (r0 & 15)) * H_DIM;
        const float* wh1 = Wh + (size_t)(lbase + (r1 & 15)) * H_DIM;
        #pragma unroll
        for (int ni = 0; ni < 4; ni++) {
            int col = nh * BN + wn + ni * 8 + 2 * tig;
            *(uint32_t*)&g_E[rg0 * H_DIM + col] = acc[mi][ni][0];
            *(uint32_t*)&g_E[rg1 * H_DIM + col] = acc[mi][ni][1];
            float2 lo = __half22float2(*(__half2*)&acc[mi][ni][0]);
            float2 hi = __half22float2(*(__half2*)&acc[mi][ni][1]);
            float2 bsv = *(const float2*)&bs[col];
            float2 w0  = *(const float2*)&wh0[col];
            float2 w1  = *(const float2*)&wh1[col];
            pap[mi*2]   += w0.x * tanhap(lo.x + bsv.x) + w0.y * tanhap(lo.y + bsv.y);
            pap[mi*2+1] += w1.x * tanhap(hi.x + bsv.x) + w1.y * tanhap(hi.y + bsv.y);
        }
    }
    #pragma unroll
    for (int j = 0; j < 8; j++) {
        pap[j] += __shfl_xor_sync(0xffffffffu, pap[j], 1);
        pap[j] += __shfl_xor_sync(0xffffffffu, pap[j], 2);
    }
    if (tig == 0) {
        #pragma unroll
        for (int mi = 0; mi < 4; mi++) {
            spa[(wm + mi * 16 + grp) * 4 + (wid >> 1)]     = pap[mi*2];
            spa[(wm + mi * 16 + grp + 8) * 4 + (wid >> 1)] = pap[mi*2+1];
        }
    }
    __syncthreads();
    if (tid < BM) {
        float s = (spa[tid*4] + spa[tid*4+1]) + (spa[tid*4+2] + spa[tid*4+3]);
        size_t rg = (size_t)(tid >> 4) * L_DIM + lbase + (tid & 15);
        g_pa[(size_t)nh * M_TOT + rg] = s;
    }
}

// ---------------- kernel 2: fused sequential recurrence (half2/float2 loads) --------
__global__ void __launch_bounds__(256) k_seq(const float* __restrict__ rois,
                                             const float* __restrict__ Wh,
                                             const float* __restrict__ bs,
                                             const float* __restrict__ bx,
                                             const float* __restrict__ by,
                                             const float* __restrict__ bz,
                                             float* __restrict__ out) {
    int wid = threadIdx.x >> 5, lane = threadIdx.x & 31;
    int l = blockIdx.x * 8 + wid;

    float wh[8], bsr[8], S[8];
    #pragma unroll
    for (int g = 0; g < 4; g++) {
        int j = g * 64 + 2 * lane;
        float2 w = *(const float2*)&Wh[(size_t)l * H_DIM + j];
        float2 b = *(const float2*)&bs[j];
        float2 s = __half22float2(*(const __half2*)&g_E[(size_t)l * H_DIM + j]);
        wh[2*g] = w.x;  wh[2*g+1] = w.y;
        bsr[2*g] = b.x; bsr[2*g+1] = b.y;
        S[2*g] = s.x;   S[2*g+1] = s.y;
    }

    float e[7][8], dxs[7], dys[7], dzs[7], pas[7];
    #pragma unroll
    for (int t = 0; t < 7; t++) {
        size_t r = (size_t)(t + 1) * L_DIM + l;
        #pragma unroll
        for (int g = 0; g < 4; g++) {
            float2 v = __half22float2(*(const __half2*)&g_E[r * H_DIM + g * 64 + 2 * lane]);
            e[t][2*g] = v.x; e[t][2*g+1] = v.y;
        }
        dxs[t] = g_dxyz[r * 3 + 0];
        dys[t] = g_dxyz[r * 3 + 1];
        dzs[t] = g_dxyz[r * 3 + 2];
        pas[t] = g_pa[r] + g_pa[M_TOT + r];
    }

    float X = g_dxyz[(size_t)l * 3 + 0];
    float Y = g_dxyz[(size_t)l * 3 + 1];
    float Z = g_dxyz[(size_t)l * 3 + 2];
    float cx = rois[(size_t)l * 3 + 0];
    float cy = rois[(size_t)l * 3 + 1];
    float cz = rois[(size_t)l * 3 + 2];
    float bxl = bx[l], byl = by[l], bzl = bz[l];
    const float s0 = 1.0f / 767.0f, s2 = 1.0f / 575.0f;

    float px = (X + bxl) * s0 + cx;
    float py = (Y + byl) * s0 + cy;
    float pz = (Z + bzl) * s2 + cz;
    if (lane == 0) {
        out[(size_t)l * 3 + 0] = px;
        out[(size_t)l * 3 + 1] = py;
        out[(size_t)l * 3 + 2] = pz;
    }

    #pragma unroll
    for (int t = 0; t < 7; t++) {
        float q[8];
        #pragma unroll
        for (int i = 0; i < 8; i++)
            q[i] = wh[i] * tanhap(S[i] + bsr[i]);
        float pf = ((q[0]+q[1]) + (q[2]+q[3])) + ((q[4]+q[5]) + (q[6]+q[7]));
        #pragma unroll
        for (int o = 16; o > 0; o >>= 1)
            pf += __shfl_xor_sync(0xffffffffu, pf, o);

        float g0 = fmaf(0.5f, tanhap(0.5f * (pf - pas[t])), 0.5f);
        float g1 = 1.0f - g0;

        #pragma unroll
        for (int i = 0; i < 8; i++) S[i] = g0 * S[i] + g1 * e[t][i];

        X = g0 * X + g1 * dxs[t];
        Y = g0 * Y + g1 * dys[t];
        Z = g0 * Z + g1 * dzs[t];
        cx = g0 * cx + g1 * px;
        cy = g0 * cy + g1 * py;
        cz = g0 * cz + g1 * pz;
        px = (X + bxl) * s0 + cx;
        py = (Y + byl) * s0 + cy;
        pz = (Z + bzl) * s2 + cz;
        if (lane == 0) {
            size_t r = (size_t)(t + 1) * L_DIM + l;
            out[r * 3 + 0] = px;
            out[r * 3 + 1] = py;
            out[r * 3 + 2] = pz;
        }
    }
}

// ---------------- launch ----------------
extern "C" void kernel_launch(void* const* d_in, const int* in_sizes, int n_in,
                              void* d_out, int out_size) {
    const float* emb  = (const float*)d_in[0];
    const float* rois = (const float*)d_in[1];
    const float* Wx   = (const float*)d_in[2];
    const float* bx   = (const float*)d_in[3];
    const float* Wy   = (const float*)d_in[4];
    const float* by   = (const float*)d_in[5];
    const float* Wz   = (const float*)d_in[6];
    const float* bz   = (const float*)d_in[7];
    const float* Ws   = (const float*)d_in[8];
    const float* bs   = (const float*)d_in[9];
    const float* Wh   = (const float*)d_in[10];
    // d_in[11] = bh: cancels in the 2-way softmax.
    float* out = (float*)d_out;

    static int attr_set = 0;
    if (!attr_set) {
        cudaFuncSetAttribute(k_gemm, cudaFuncAttributeMaxDynamicSharedMemorySize, SMEM_TOTAL);
        attr_set = 1;
    }

    k_prep<<<L_DIM + 128, 256>>>(emb, Wx, Wy, Wz, Ws);
    k_gemm<<<dim3(2, L_DIM / 16), 256, SMEM_TOTAL>>>(Wh, bs);
    k_seq<<<L_DIM / 8, 256>>>(rois, Wh, bs, bx, by, bz, out);
}

// round 16
// speedup vs baseline: 1.1294x; 1.1294x over previous
#include <cuda_runtime.h>
#include <cuda_fp16.h>
#include <cstdint>

#define T_ITER 8
#define L_DIM  4096
#define D_DIM  512
#define H_DIM  256
#define M_TOT  (T_ITER * L_DIM)

#define WS_SCALE    8.0f
#define WS_INV      0.125f

// ---------------- scratch ----------------
__device__ uint8_t g_A8[(size_t)M_TOT * D_DIM];         // emb e4m3, 16 MB
__device__ __half  g_E[(size_t)M_TOT * H_DIM];          // emb @ Ws (descaled), f16, 16 MB
__device__ float   g_dxyz[(size_t)M_TOT * 3];
__device__ float   g_pa[4 * M_TOT];                     // gate logit, 4 col-quarters
__device__ uint8_t g_B8[H_DIM * D_DIM];                 // (8*Ws)^T e4m3, [n][k]

__device__ __forceinline__ float tanhap(float x) {
    float y; asm("tanh.approx.f32 %0, %1;" : "=f"(y) : "f"(x)); return y;
}
// pack two floats -> e4m3x2 (lo byte = 'lo' arg)  [verified in R9]
__device__ __forceinline__ uint16_t f2e4m3x2(float lo, float hi) {
    uint16_t r;
    asm("cvt.rn.satfinite.e4m3x2.f32 %0, %1, %2;" : "=h"(r) : "f"(hi), "f"(lo));
    return r;
}

// ---------------- kernel 0: prep (A fp32->e4m3 + dec dots) UNION Ws transpose -------
__global__ void __launch_bounds__(256) k_prep(const float* __restrict__ A,
                                              const float* __restrict__ Wx,
                                              const float* __restrict__ Wy,
                                              const float* __restrict__ Wz,
                                              const float* __restrict__ Ws) {
    __shared__ float sw[3][D_DIM];
    const int tid = threadIdx.x, lane = tid & 31;
    if (blockIdx.x >= L_DIM) {
        // ---- Ws (512x256 [k][n]) -> g_B8 ([n][k]) e4m3 scaled x8 ----
        const int cb = blockIdx.x - L_DIM;       // 0..127
        const int bx = cb & 7, by = cb >> 3;
        const int tx = tid & 31, ty = tid >> 5;  // 32 x 8
        float (*tile)[33] = (float(*)[33])sw;
        #pragma unroll
        for (int i = 0; i < 4; i++) {
            int k = by * 32 + ty + i * 8;
            tile[ty + i * 8][tx] = Ws[k * H_DIM + bx * 32 + tx];
        }
        __syncthreads();
        if (tx < 16) {
            #pragma unroll
            for (int i = 0; i < 4; i++) {
                int n = bx * 32 + ty + i * 8;
                uint16_t v = f2e4m3x2(WS_SCALE * tile[2 * tx][ty + i * 8],
                                      WS_SCALE * tile[2 * tx + 1][ty + i * 8]);
                *(uint16_t*)&g_B8[n * D_DIM + by * 32 + 2 * tx] = v;
            }
        }
        return;
    }
    const int l = blockIdx.x;
    const int t = tid >> 5;                      // warp = time step
    for (int i = tid; i < D_DIM; i += 256) {
        sw[0][i] = Wx[(size_t)l * D_DIM + i];
        sw[1][i] = Wy[(size_t)l * D_DIM + i];
        sw[2][i] = Wz[(size_t)l * D_DIM + i];
    }
    __syncthreads();

    const size_t row = (size_t)t * L_DIM + l;
    const float* a = A + row * D_DIM;
    uint8_t* a8 = g_A8 + row * D_DIM;
    float dx = 0.f, dy = 0.f, dz = 0.f;
    #pragma unroll
    for (int j = 0; j < 4; j++) {
        int off = j * 128 + lane * 4;
        float4 v = *(const float4*)(a + off);
        dx += v.x * sw[0][off] + v.y * sw[0][off+1] + v.z * sw[0][off+2] + v.w * sw[0][off+3];
        dy += v.x * sw[1][off] + v.y * sw[1][off+1] + v.z * sw[1][off+2] + v.w * sw[1][off+3];
        dz += v.x * sw[2][off] + v.y * sw[2][off+1] + v.z * sw[2][off+2] + v.w * sw[2][off+3];
        uint32_t p = (uint32_t)f2e4m3x2(v.x, v.y) | ((uint32_t)f2e4m3x2(v.z, v.w) << 16);
        *(uint32_t*)(a8 + off) = p;
    }
    #pragma unroll
    for (int o = 16; o > 0; o >>= 1) {
        dx += __shfl_xor_sync(0xffffffffu, dx, o);
        dy += __shfl_xor_sync(0xffffffffu, dy, o);
        dz += __shfl_xor_sync(0xffffffffu, dz, o);
    }
    if (lane == 0) {
        g_dxyz[row * 3 + 0] = dx;
        g_dxyz[row * 3 + 1] = dy;
        g_dxyz[row * 3 + 2] = dz;
    }
}

// ---------------- kernel 1: fp8 GEMM, R14 pipeline (3-stage, 1 bar/kt), occ 4 -------
#define BM 128
#define BN 64                                    // N quarter per CTA
#define BKB 64                                   // K bytes per kt
#define RS 80                                    // smem row stride bytes
#define SZ_A (BM * RS)                           // 10240
#define SZ_B (BN * RS)                           // 5120
#define SZ_STG (SZ_A + SZ_B)                     // 15360
#define NSTAGE 3
#define OFF_SPA (NSTAGE * SZ_STG)
#define SMEM_TOTAL (OFF_SPA + BM * 4 * 4)        // 48128
#define NKT (D_DIM / BKB)                        // 8

__device__ __forceinline__ void mma_e4m3(float c[4],
                                         uint32_t a0, uint32_t a1, uint32_t a2, uint32_t a3,
                                         uint32_t b0, uint32_t b1) {
    asm volatile(
        "mma.sync.aligned.m16n8k32.row.col.f32.e4m3.e4m3.f32 "
        "{%0,%1,%2,%3}, {%4,%5,%6,%7}, {%8,%9}, {%0,%1,%2,%3};\n"
        : "+f"(c[0]), "+f"(c[1]), "+f"(c[2]), "+f"(c[3])
        : "r"(a0), "r"(a1), "r"(a2), "r"(a3), "r"(b0), "r"(b1));
}
__device__ __forceinline__ void ldsm_x4(uint32_t addr, uint32_t& r0, uint32_t& r1,
                                        uint32_t& r2, uint32_t& r3) {
    asm volatile("ldmatrix.sync.aligned.m8n8.x4.shared.b16 {%0,%1,%2,%3}, [%4];"
                 : "=r"(r0), "=r"(r1), "=r"(r2), "=r"(r3) : "r"(addr));
}
__device__ __forceinline__ void cp16(uint32_t dst, const void* src) {
    asm volatile("cp.async.ca.shared.global [%0], [%1], 16;" :: "r"(dst), "l"(src) : "memory");
}

__global__ void __launch_bounds__(256, 4) k_gemm(const float* __restrict__ Wh,
                                                 const float* __restrict__ bs) {
    extern __shared__ __align__(128) char smem[];
    uint32_t sbase;
    asm("{ .reg .u64 t; cvta.to.shared.u64 t, %1; cvt.u32.u64 %0, t; }" : "=r"(sbase) : "l"(smem));

    const int tid  = threadIdx.x;
    const int lane = tid & 31, wid = tid >> 5;
    const int grp  = lane >> 2, tig = lane & 3;
    const int nq    = blockIdx.x;                 // N quarter (fastest -> L2 shares A8)
    const int lbase = blockIdx.y * 16;            // 16 l's x 8 t's

    // A staging: thread covers 32 B of local row (tid>>1)
    const int arow = tid >> 1;
    const int ahalf = (tid & 1) * 32;
    const size_t argRow = (size_t)(arow >> 4) * L_DIM + lbase + (arow & 15);
    const uint8_t* Asrc = g_A8 + argRow * D_DIM + ahalf;
    const uint32_t aDst = (uint32_t)(arow * RS) + ahalf;
    // B staging: thread covers 16 B of row (tid>>2)
    const int bn = tid >> 2;
    const int bseg = (tid & 3) * 16;
    const uint8_t* Bsrc = g_B8 + (size_t)(nq * BN + bn) * D_DIM + bseg;
    const uint32_t bDst = (uint32_t)(bn * RS) + bseg;

    // ldmatrix lane addressing (byte form; same mapping verified in R9)
    const int aRowL = lane & 15;
    const int aColB = (lane >> 4) * 16;           // byte column half
    const int bRowL = (lane & 7) + ((lane >> 4) << 3);
    const int bColB = ((lane >> 3) & 1) * 16;
    uint32_t stg[NSTAGE];
    #pragma unroll
    for (int s = 0; s < NSTAGE; s++) stg[s] = sbase + s * SZ_STG;

    // warp tile 64x16: 2 M-warps x 4 N-warps
    const int wm = (wid & 1) * 64;
    const int wn = (wid >> 1) * 16;

    float acc[4][2][4];
    #pragma unroll
    for (int i = 0; i < 4; i++)
        #pragma unroll
        for (int j = 0; j < 2; j++)
            #pragma unroll
            for (int r = 0; r < 4; r++) acc[i][j][r] = 0.f;

    // ---- prologue: stages 0,1 ----
    #pragma unroll
    for (int p = 0; p < 2; p++) {
        cp16(stg[p] + aDst,      Asrc + p * BKB);
        cp16(stg[p] + aDst + 16, Asrc + p * BKB + 16);
        cp16(stg[p] + SZ_A + bDst, Bsrc + p * BKB);
        asm volatile("cp.async.commit_group;" ::: "memory");
    }

    for (int kt = 0; kt < NKT; kt++) {
        const int s = kt % NSTAGE;
        asm volatile("cp.async.wait_group 1;" ::: "memory");
        __syncthreads();
        if (kt + 2 < NKT) {
            const int sn = (kt + 2) % NSTAGE;
            cp16(stg[sn] + aDst,      Asrc + (kt + 2) * BKB);
            cp16(stg[sn] + aDst + 16, Asrc + (kt + 2) * BKB + 16);
            cp16(stg[sn] + SZ_A + bDst, Bsrc + (kt + 2) * BKB);
            asm volatile("cp.async.commit_group;" ::: "memory");
        } else {
            asm volatile("cp.async.commit_group;" ::: "memory");  // keep group count in step
        }

        #pragma unroll
        for (int ks = 0; ks < 2; ks++) {
            // B fragments: one ldsm_x4 covers both ni blocks (16 n-rows)
            uint32_t bf[2][2];
            {
                uint32_t addr = stg[s] + SZ_A + (uint32_t)((wn + bRowL) * RS + ks * 32 + bColB);
                ldsm_x4(addr, bf[0][0], bf[0][1], bf[1][0], bf[1][1]);
            }
            #pragma unroll
            for (int mi = 0; mi < 4; mi++) {
                uint32_t a0, a1, a2, a3;
                uint32_t addr = stg[s] + (uint32_t)((wm + mi * 16 + aRowL) * RS + ks * 32 + aColB);
                ldsm_x4(addr, a0, a1, a2, a3);
                #pragma unroll
                for (int ni = 0; ni < 2; ni++)
                    mma_e4m3(acc[mi][ni], a0, a1, a2, a3, bf[ni][0], bf[ni][1]);
            }
        }
    }

    // ---- epilogue: descale, store E (f16) + pa partials ----
    float* spa = (float*)(smem + OFF_SPA);        // [128][4]
    float pap[8];
    #pragma unroll
    for (int j = 0; j < 8; j++) pap[j] = 0.f;
    #pragma unroll
    for (int mi = 0; mi < 4; mi++) {
        const int r0 = wm + mi * 16 + grp;
        const int r1 = r0 + 8;
        const size_t rg0 = (size_t)(r0 >> 4) * L_DIM + lbase + (r0 & 15);
        const size_t rg1 = (size_t)(r1 >> 4) * L_DIM + lbase + (r1 & 15);
        const float* wh0 = Wh + (size_t)(lbase + (r0 & 15)) * H_DIM;
        const float* wh1 = Wh + (size_t)(lbase + (r1 & 15)) * H_DIM;
        #pragma unroll
        for (int ni = 0; ni < 2; ni++) {
            int col = nq * BN + wn + ni * 8 + 2 * tig;
            float e00 = acc[mi][ni][0] * WS_INV, e01 = acc[mi][ni][1] * WS_INV;
            float e10 = acc[mi][ni][2] * WS_INV, e11 = acc[mi][ni][3] * WS_INV;
            __half2 h0 = __float22half2_rn(make_float2(e00, e01));
            __half2 h1 = __float22half2_rn(make_float2(e10, e11));
            *(uint32_t*)&g_E[rg0 * H_DIM + col] = *(uint32_t*)&h0;
            *(uint32_t*)&g_E[rg1 * H_DIM + col] = *(uint32_t*)&h1;
            float2 bsv = *(const float2*)&bs[col];
            float2 w0  = *(const float2*)&wh0[col];
            float2 w1  = *(const float2*)&wh1[col];
            pap[mi*2]   += w0.x * tanhap(e00 + bsv.x) + w0.y * tanhap(e01 + bsv.y);
            pap[mi*2+1] += w1.x * tanhap(e10 + bsv.x) + w1.y * tanhap(e11 + bsv.y);
        }
    }
    #pragma unroll
    for (int j = 0; j < 8; j++) {
        pap[j] += __shfl_xor_sync(0xffffffffu, pap[j], 1);
        pap[j] += __shfl_xor_sync(0xffffffffu, pap[j], 2);
    }
    if (tig == 0) {
        #pragma unroll
        for (int mi = 0; mi < 4; mi++) {
            spa[(wm + mi * 16 + grp) * 4 + (wid >> 1)]     = pap[mi*2];
            spa[(wm + mi * 16 + grp + 8) * 4 + (wid >> 1)] = pap[mi*2+1];
        }
    }
    __syncthreads();
    if (tid < BM) {
        float s = (spa[tid*4] + spa[tid*4+1]) + (spa[tid*4+2] + spa[tid*4+3]);
        size_t rg = (size_t)(tid >> 4) * L_DIM + lbase + (tid & 15);
        g_pa[(size_t)nq * M_TOT + rg] = s;
    }
}

// ---------------- kernel 2: fused sequential recurrence (half2/float2 loads) --------
__global__ void __launch_bounds__(256) k_seq(const float* __restrict__ rois,
                                             const float* __restrict__ Wh,
                                             const float* __restrict__ bs,
                                             const float* __restrict__ bx,
                                             const float* __restrict__ by,
                                             const float* __restrict__ bz,
                                             float* __restrict__ out) {
    int wid = threadIdx.x >> 5, lane = threadIdx.x & 31;
    int l = blockIdx.x * 8 + wid;

    float wh[8], bsr[8], S[8];
    #pragma unroll
    for (int g = 0; g < 4; g++) {
        int j = g * 64 + 2 * lane;
        float2 w = *(const float2*)&Wh[(size_t)l * H_DIM + j];
        float2 b = *(const float2*)&bs[j];
        float2 s = __half22float2(*(const __half2*)&g_E[(size_t)l * H_DIM + j]);
        wh[2*g] = w.x;  wh[2*g+1] = w.y;
        bsr[2*g] = b.x; bsr[2*g+1] = b.y;
        S[2*g] = s.x;   S[2*g+1] = s.y;
    }

    float e[7][8], dxs[7], dys[7], dzs[7], pas[7];
    #pragma unroll
    for (int t = 0; t < 7; t++) {
        size_t r = (size_t)(t + 1) * L_DIM + l;
        #pragma unroll
        for (int g = 0; g < 4; g++) {
            float2 v = __half22float2(*(const __half2*)&g_E[r * H_DIM + g * 64 + 2 * lane]);
            e[t][2*g] = v.x; e[t][2*g+1] = v.y;
        }
        dxs[t] = g_dxyz[r * 3 + 0];
        dys[t] = g_dxyz[r * 3 + 1];
        dzs[t] = g_dxyz[r * 3 + 2];
        pas[t] = (g_pa[r] + g_pa[M_TOT + r]) + (g_pa[2 * M_TOT + r] + g_pa[3 * M_TOT + r]);
    }

    float X = g_dxyz[(size_t)l * 3 + 0];
    float Y = g_dxyz[(size_t)l * 3 + 1];
    float Z = g_dxyz[(size_t)l * 3 + 2];
    float cx = rois[(size_t)l * 3 + 0];
    float cy = rois[(size_t)l * 3 + 1];
    float cz = rois[(size_t)l * 3 + 2];
    float bxl = bx[l], byl = by[l], bzl = bz[l];
    const float s0 = 1.0f / 767.0f, s2 = 1.0f / 575.0f;

    float px = (X + bxl) * s0 + cx;
    float py = (Y + byl) * s0 + cy;
    float pz = (Z + bzl) * s2 + cz;
    if (lane == 0) {
        out[(size_t)l * 3 + 0] = px;
        out[(size_t)l * 3 + 1] = py;
        out[(size_t)l * 3 + 2] = pz;
    }

    #pragma unroll
    for (int t = 0; t < 7; t++) {
        float q[8];
        #pragma unroll
        for (int i = 0; i < 8; i++)
            q[i] = wh[i] * tanhap(S[i] + bsr[i]);
        float pf = ((q[0]+q[1]) + (q[2]+q[3])) + ((q[4]+q[5]) + (q[6]+q[7]));
        #pragma unroll
        for (int o = 16; o > 0; o >>= 1)
            pf += __shfl_xor_sync(0xffffffffu, pf, o);

        float g0 = fmaf(0.5f, tanhap(0.5f * (pf - pas[t])), 0.5f);
        float g1 = 1.0f - g0;

        #pragma unroll
        for (int i = 0; i < 8; i++) S[i] = g0 * S[i] + g1 * e[t][i];

        X = g0 * X + g1 * dxs[t];
        Y = g0 * Y + g1 * dys[t];
        Z = g0 * Z + g1 * dzs[t];
        cx = g0 * cx + g1 * px;
        cy = g0 * cy + g1 * py;
        cz = g0 * cz + g1 * pz;
        px = (X + bxl) * s0 + cx;
        py = (Y + byl) * s0 + cy;
        pz = (Z + bzl) * s2 + cz;
        if (lane == 0) {
            size_t r = (size_t)(t + 1) * L_DIM + l;
            out[r * 3 + 0] = px;
            out[r * 3 + 1] = py;
            out[r * 3 + 2] = pz;
        }
    }
}

// ---------------- launch ----------------
extern "C" void kernel_launch(void* const* d_in, const int* in_sizes, int n_in,
                              void* d_out, int out_size) {
    const float* emb  = (const float*)d_in[0];
    const float* rois = (const float*)d_in[1];
    const float* Wx   = (const float*)d_in[2];
    const float* bx   = (const float*)d_in[3];
    const float* Wy   = (const float*)d_in[4];
    const float* by   = (const float*)d_in[5];
    const float* Wz   = (const float*)d_in[6];
    const float* bz   = (const float*)d_in[7];
    const float* Ws   = (const float*)d_in[8];
    const float* bs   = (const float*)d_in[9];
    const float* Wh   = (const float*)d_in[10];
    // d_in[11] = bh: cancels in the 2-way softmax.
    float* out = (float*)d_out;

    static int attr_set = 0;
    if (!attr_set) {
        cudaFuncSetAttribute(k_gemm, cudaFuncAttributeMaxDynamicSharedMemorySize, SMEM_TOTAL);
        attr_set = 1;
    }

    k_prep<<<L_DIM + 128, 256>>>(emb, Wx, Wy, Wz, Ws);
    k_gemm<<<dim3(4, L_DIM / 16), 256, SMEM_TOTAL>>>(Wh, bs);
    k_seq<<<L_DIM / 8, 256>>>(rois, Wh, bs, bx, by, bz, out);
}